// round 1
// baseline (speedup 1.0000x reference)
#include <cuda_runtime.h>
#include <math.h>

#define TSZ 2048
#define HN  16
#define DH  64

// Scratch: 5 projections in (B,H,T,64) layout + o2d in (B*T, H*64) layout.
__device__ float g_proj[5][(size_t)64 * TSZ * DH];   // 5 * 32 MB
__device__ float g_o2d[(size_t)8192 * 1024];         // 32 MB

// ---------------------------------------------------------------------------
// fp32 SGEMM: C = A(MxK) * B(KxN) [+ bias, sigmoid], 128x128x16 tiles,
// 256 threads, 8x8 per-thread microtile.
// mode 0: plain row-major store to C (M x N)
// mode 1: permuted store: row m=(b*2048+t), col n=(h*64+d) -> C[((b*16+h)*2048+t)*64+d]
// mode 2: mode 1 + sigmoid(acc + bias[n])
// Requires M%128==0, N%128==0, K%16==0 (true here: 8192,1024,1024).
// ---------------------------------------------------------------------------
__global__ __launch_bounds__(256) void sgemm_kernel(
    const float* __restrict__ A, const float* __restrict__ B,
    const float* __restrict__ bias, float* __restrict__ C,
    int M, int N, int K, int mode)
{
    __shared__ float As[16][128];
    __shared__ float Bs[16][128];
    const int tid = threadIdx.x;
    const int blockRow = blockIdx.y * 128;
    const int blockCol = blockIdx.x * 128;
    const int tr = tid >> 4;    // 0..15
    const int tc = tid & 15;    // 0..15

    float acc[8][8];
#pragma unroll
    for (int i = 0; i < 8; i++)
#pragma unroll
        for (int j = 0; j < 8; j++) acc[i][j] = 0.f;

    const int arow  = tid >> 2;         // 0..63
    const int acol4 = (tid & 3) << 2;   // 0,4,8,12
    const int brow  = tid >> 5;         // 0..7
    const int bcol4 = (tid & 31) << 2;  // 0..124

    for (int k0 = 0; k0 < K; k0 += 16) {
        const float* Ag = A + (size_t)(blockRow + arow) * K + k0 + acol4;
        float4 a0 = *(const float4*)Ag;
        float4 a1 = *(const float4*)(Ag + (size_t)64 * K);
        As[acol4 + 0][arow] = a0.x;
        As[acol4 + 1][arow] = a0.y;
        As[acol4 + 2][arow] = a0.z;
        As[acol4 + 3][arow] = a0.w;
        As[acol4 + 0][arow + 64] = a1.x;
        As[acol4 + 1][arow + 64] = a1.y;
        As[acol4 + 2][arow + 64] = a1.z;
        As[acol4 + 3][arow + 64] = a1.w;

        const float* Bg = B + (size_t)(k0 + brow) * N + blockCol + bcol4;
        *(float4*)&Bs[brow][bcol4]     = *(const float4*)Bg;
        *(float4*)&Bs[brow + 8][bcol4] = *(const float4*)(Bg + (size_t)8 * N);
        __syncthreads();

#pragma unroll
        for (int kk = 0; kk < 16; kk++) {
            float ra[8], rb[8];
#pragma unroll
            for (int m = 0; m < 8; m++) ra[m] = As[kk][tr * 8 + m];
#pragma unroll
            for (int n = 0; n < 8; n++) rb[n] = Bs[kk][tc * 8 + n];
#pragma unroll
            for (int m = 0; m < 8; m++)
#pragma unroll
                for (int n = 0; n < 8; n++)
                    acc[m][n] = fmaf(ra[m], rb[n], acc[m][n]);
        }
        __syncthreads();
    }

#pragma unroll
    for (int m = 0; m < 8; m++) {
        int gr = blockRow + tr * 8 + m;
#pragma unroll
        for (int n = 0; n < 8; n++) {
            int gc = blockCol + tc * 8 + n;
            float v = acc[m][n];
            if (mode == 0) {
                C[(size_t)gr * N + gc] = v;
            } else {
                if (mode == 2) v = 1.f / (1.f + __expf(-(v + bias[gc])));
                int b = gr >> 11, t = gr & 2047;   // T = 2048
                int h = gc >> 6,  d = gc & 63;
                C[((size_t)((b * HN + h) * TSZ + t)) * DH + d] = v;
            }
        }
    }
}

// ---------------------------------------------------------------------------
// Scan kernel: one CTA per (b,h). 256 threads = 4 row-groups x 64 columns.
// Thread (ty,tx) owns rows i in [16*ty, 16*ty+16) of column tx for the three
// 64x64 states S_K, C_QV, G (all in registers).
//
// Per step:
//   kc = k^T (aC . C_QV_old)                      (reduction 1)
//   C_QV = aC.C_QV + q v^T ;  G = aK.G + k kc^T ; S_K = (aK aK^T).S_K + k k^T
//   u = q^T S_K ; qg = q^T G                      (reduction 2)
//   o = u C_QV - qg                               (reduction 3)
// ---------------------------------------------------------------------------
__global__ __launch_bounds__(256) void scan_kernel(
    const float* __restrict__ qp, const float* __restrict__ kp,
    const float* __restrict__ vp, const float* __restrict__ aKp,
    const float* __restrict__ aCp, float* __restrict__ o2d)
{
    const int bh = blockIdx.x;          // 0..63
    const int b = bh >> 4, h = bh & 15;
    const size_t base = (size_t)bh * TSZ * DH;
    const int tid = threadIdx.x;
    const int ty = tid >> 6;            // 0..3
    const int tx = tid & 63;            // 0..63

    __shared__ float svec[5][64];       // q,k,v,aK,aC for current t
    __shared__ float skc[64], su[64], sqg[64];
    __shared__ float red[3][4][64];

    float Sk[16], Cq[16], G[16];
#pragma unroll
    for (int r = 0; r < 16; r++) { Sk[r] = 0.f; Cq[r] = 0.f; G[r] = 0.f; }

    float* svf = &svec[0][0];

    for (int t = 0; t < TSZ; t++) {
        const size_t voff = base + (size_t)t * DH;
        // load the 5 length-64 vectors (320 loads over 256 threads)
        {
            int idx = tid;
            const float* p = (idx < 64) ? qp : (idx < 128) ? kp : (idx < 192) ? vp : aKp;
            svf[idx] = p[voff + (idx & 63)];
            idx = tid + 256;
            if (idx < 320) svf[idx] = aCp[voff + (idx & 63)];
        }
        __syncthreads();

        const float* sq  = svec[0];
        const float* sk  = svec[1];
        const float* sv  = svec[2];
        const float* saK = svec[3];
        const float* saC = svec[4];

        // ---- reduction 1: kc[tx] = sum_i k[i]*aC[i]*Cq_old[i][tx]
        float p1 = 0.f;
#pragma unroll
        for (int r = 0; r < 16; r++) {
            int i = ty * 16 + r;
            p1 += sk[i] * saC[i] * Cq[r];
        }
        red[0][ty][tx] = p1;
        __syncthreads();
        if (ty == 0)
            skc[tx] = red[0][0][tx] + red[0][1][tx] + red[0][2][tx] + red[0][3][tx];
        __syncthreads();

        // ---- state updates + partials for u and qg
        const float vtx   = sv[tx];
        const float ktx   = sk[tx];
        const float aKtx  = saK[tx];
        const float kctx  = skc[tx];
        float pu = 0.f, pg = 0.f;
#pragma unroll
        for (int r = 0; r < 16; r++) {
            int i = ty * 16 + r;
            float qi = sq[i], ki = sk[i], aKi = saK[i], aCi = saC[i];
            Cq[r] = aCi * Cq[r] + qi * vtx;
            G[r]  = aKi * G[r]  + ki * kctx;
            Sk[r] = aKi * aKtx * Sk[r] + ki * ktx;
            pu += qi * Sk[r];
            pg += qi * G[r];
        }
        red[0][ty][tx] = pu;
        red[1][ty][tx] = pg;
        __syncthreads();
        if (ty == 0) {
            su[tx]  = red[0][0][tx] + red[0][1][tx] + red[0][2][tx] + red[0][3][tx];
            sqg[tx] = red[1][0][tx] + red[1][1][tx] + red[1][2][tx] + red[1][3][tx];
        }
        __syncthreads();

        // ---- reduction 3: o[tx] = sum_j u[j]*Cq_new[j][tx] - qg[tx]
        float p3 = 0.f;
#pragma unroll
        for (int r = 0; r < 16; r++) {
            int i = ty * 16 + r;
            p3 += su[i] * Cq[r];
        }
        red[2][ty][tx] = p3;
        __syncthreads();
        if (ty == 0) {
            float o = red[2][0][tx] + red[2][1][tx] + red[2][2][tx] + red[2][3][tx] - sqg[tx];
            o2d[(size_t)(b * TSZ + t) * 1024 + h * DH + tx] = o;
        }
        // no trailing barrier needed: next-iter svec writes touch disjoint
        // arrays from the red/sqg reads above, and the load-barrier realigns.
    }
}

// ---------------------------------------------------------------------------
extern "C" void kernel_launch(void* const* d_in, const int* in_sizes, int n_in,
                              void* d_out, int out_size)
{
    const float* x   = (const float*)d_in[0];
    const float* Wq  = (const float*)d_in[1];
    const float* Wk  = (const float*)d_in[2];
    const float* Wv  = (const float*)d_in[3];
    const float* WgK = (const float*)d_in[4];
    const float* bgK = (const float*)d_in[5];
    const float* WgC = (const float*)d_in[6];
    const float* bgC = (const float*)d_in[7];
    const float* Wo  = (const float*)d_in[8];
    float* out = (float*)d_out;

    float* proj = nullptr;
    float* o2d  = nullptr;
    cudaGetSymbolAddress((void**)&proj, g_proj);
    cudaGetSymbolAddress((void**)&o2d,  g_o2d);
    const size_t PS = (size_t)64 * TSZ * DH;

    const int M = 8192, N = 1024, K = 1024;
    dim3 grid(N / 128, M / 128), blk(256);

    sgemm_kernel<<<grid, blk>>>(x, Wq,  nullptr, proj + 0 * PS, M, N, K, 1);
    sgemm_kernel<<<grid, blk>>>(x, Wk,  nullptr, proj + 1 * PS, M, N, K, 1);
    sgemm_kernel<<<grid, blk>>>(x, Wv,  nullptr, proj + 2 * PS, M, N, K, 1);
    sgemm_kernel<<<grid, blk>>>(x, WgK, bgK,     proj + 3 * PS, M, N, K, 2);
    sgemm_kernel<<<grid, blk>>>(x, WgC, bgC,     proj + 4 * PS, M, N, K, 2);

    scan_kernel<<<64, 256>>>(proj, proj + PS, proj + 2 * PS,
                             proj + 3 * PS, proj + 4 * PS, o2d);

    sgemm_kernel<<<grid, blk>>>(o2d, Wo, nullptr, out, M, N, K, 0);
}

// round 2
// speedup vs baseline: 1.9135x; 1.9135x over previous
#include <cuda_runtime.h>
#include <math.h>

#define TSZ 2048
#define HN  16
#define DH  64

// Scratch: 5 projections in (B,H,T,64) layout + o2d in (B*T, H*64) layout.
__device__ float g_proj[5][(size_t)64 * TSZ * DH];   // 5 * 32 MB
__device__ float g_o2d[(size_t)8192 * 1024];         // 32 MB

__device__ __forceinline__ float f2tf32(float f) {
    unsigned u;
    asm("cvt.rna.tf32.f32 %0, %1;" : "=r"(u) : "f"(f));
    return __uint_as_float(u);
}
__device__ __forceinline__ float4 cvt4(float4 v) {
    float4 r;
    r.x = f2tf32(v.x); r.y = f2tf32(v.y); r.z = f2tf32(v.z); r.w = f2tf32(v.w);
    return r;
}

// ---------------------------------------------------------------------------
// TF32 tensor-core GEMM: C = A(MxK) * B(KxN) [+ bias, sigmoid]
// 128x128 CTA tile, ktile=32, 8 warps as 2(m) x 4(n) -> warp tile 64x32.
// mma.sync m16n8k8 tf32. Register-prefetched global->smem pipeline.
// mode 0: row-major store; mode 1: permuted (b,h,t,d); mode 2: mode1+sigmoid.
// ---------------------------------------------------------------------------
__global__ __launch_bounds__(256) void gemm_tf32_kernel(
    const float* __restrict__ A, const float* __restrict__ B,
    const float* __restrict__ bias, float* __restrict__ C,
    int M, int N, int K, int mode)
{
    __shared__ float As[128][36];   // [m][k], pad 4 -> frag loads conflict-free
    __shared__ float Bs[32][136];   // [k][n], pad 8 -> frag loads conflict-free

    const int tid  = threadIdx.x;
    const int lane = tid & 31;
    const int warpId = tid >> 5;
    const int wm = warpId & 1;       // 0..1: m offset 64*wm
    const int wn = warpId >> 1;      // 0..3: n offset 32*wn
    const int g  = lane >> 2;        // 0..7
    const int tg = lane & 3;         // 0..3
    const int rowBase = blockIdx.y * 128;
    const int colBase = blockIdx.x * 128;

    float acc[4][4][4];
#pragma unroll
    for (int i = 0; i < 4; i++)
#pragma unroll
        for (int j = 0; j < 4; j++)
#pragma unroll
            for (int e = 0; e < 4; e++) acc[i][j][e] = 0.f;

    // global load mapping
    const int am  = tid >> 1;            // A row 0..127
    const int ak0 = (tid & 1) << 4;      // A k base 0 or 16
    const int bk  = tid >> 3;            // B k row 0..31
    const int bn0 = (tid & 7) << 2;      // B n base 0..28

    const float* Aptr = A + (size_t)(rowBase + am) * K + ak0;
    const float* Bptr = B + (size_t)bk * N + colBase + bn0;

    float4 ra[4], rb[4];
#pragma unroll
    for (int i = 0; i < 4; i++) ra[i] = *(const float4*)(Aptr + i * 4);
#pragma unroll
    for (int i = 0; i < 4; i++) rb[i] = *(const float4*)(Bptr + i * 32);

    const int KT = K >> 5;
    for (int kt = 0; kt < KT; kt++) {
        // STS current tile (with tf32 rounding)
        {
            float* as = &As[am][ak0];
#pragma unroll
            for (int i = 0; i < 4; i++) *(float4*)(as + i * 4) = cvt4(ra[i]);
            float* bs = &Bs[bk][bn0];
#pragma unroll
            for (int i = 0; i < 4; i++) *(float4*)(bs + (i << 5)) = cvt4(rb[i]);
        }
        __syncthreads();

        // prefetch next tile (overlaps MMA below)
        if (kt + 1 < KT) {
            Aptr += 32;
            Bptr += (size_t)32 * N;
#pragma unroll
            for (int i = 0; i < 4; i++) ra[i] = *(const float4*)(Aptr + i * 4);
#pragma unroll
            for (int i = 0; i < 4; i++) rb[i] = *(const float4*)(Bptr + i * 32);
        }

#pragma unroll
        for (int kk = 0; kk < 4; kk++) {
            unsigned af[4][4];
#pragma unroll
            for (int mi = 0; mi < 4; mi++) {
                const int m0 = wm * 64 + mi * 16 + g;
                const float* a0 = &As[m0][kk * 8 + tg];
                const float* a1 = &As[m0 + 8][kk * 8 + tg];
                af[mi][0] = __float_as_uint(a0[0]);
                af[mi][1] = __float_as_uint(a1[0]);
                af[mi][2] = __float_as_uint(a0[4]);
                af[mi][3] = __float_as_uint(a1[4]);
            }
            unsigned bf[4][2];
#pragma unroll
            for (int ni = 0; ni < 4; ni++) {
                const int n0 = wn * 32 + ni * 8 + g;
                bf[ni][0] = __float_as_uint(Bs[kk * 8 + tg][n0]);
                bf[ni][1] = __float_as_uint(Bs[kk * 8 + tg + 4][n0]);
            }
#pragma unroll
            for (int mi = 0; mi < 4; mi++)
#pragma unroll
                for (int ni = 0; ni < 4; ni++) {
                    asm volatile(
                        "mma.sync.aligned.m16n8k8.row.col.f32.tf32.tf32.f32 "
                        "{%0,%1,%2,%3}, {%4,%5,%6,%7}, {%8,%9}, {%0,%1,%2,%3};\n"
                        : "+f"(acc[mi][ni][0]), "+f"(acc[mi][ni][1]),
                          "+f"(acc[mi][ni][2]), "+f"(acc[mi][ni][3])
                        : "r"(af[mi][0]), "r"(af[mi][1]),
                          "r"(af[mi][2]), "r"(af[mi][3]),
                          "r"(bf[ni][0]), "r"(bf[ni][1]));
                }
        }
        __syncthreads();
    }

    // epilogue
#pragma unroll
    for (int mi = 0; mi < 4; mi++) {
        const int gr0 = rowBase + wm * 64 + mi * 16 + g;
#pragma unroll
        for (int ni = 0; ni < 4; ni++) {
            const int gc = colBase + wn * 32 + ni * 8 + 2 * tg;  // even
#pragma unroll
            for (int half = 0; half < 2; half++) {
                const int gr = gr0 + 8 * half;
                float v0 = acc[mi][ni][2 * half];
                float v1 = acc[mi][ni][2 * half + 1];
                if (mode == 0) {
                    float2 st = make_float2(v0, v1);
                    *(float2*)&C[(size_t)gr * N + gc] = st;
                } else {
                    if (mode == 2) {
                        v0 = 1.f / (1.f + __expf(-(v0 + bias[gc])));
                        v1 = 1.f / (1.f + __expf(-(v1 + bias[gc + 1])));
                    }
                    const int b = gr >> 11, t = gr & 2047;
                    const int h = gc >> 6,  d = gc & 63;   // d even, d+1 same h
                    float2 st = make_float2(v0, v1);
                    *(float2*)&C[((size_t)((b * HN + h) * TSZ + t)) * DH + d] = st;
                }
            }
        }
    }
}

// ---------------------------------------------------------------------------
// Scan kernel: one CTA per (b,h), 256 threads = 4 row-groups x 64 cols.
// Software-pipelined: LDG for step t+2 issued at top of step t; smem vector
// block double-buffered. 4 barriers/step; reductions summed redundantly.
// ---------------------------------------------------------------------------
__global__ __launch_bounds__(256) void scan_kernel(
    const float* __restrict__ qp, const float* __restrict__ kp,
    const float* __restrict__ vp, const float* __restrict__ aKp,
    const float* __restrict__ aCp, float* __restrict__ o2d)
{
    const int bh = blockIdx.x;          // 0..63
    const int b = bh >> 4, h = bh & 15;
    const size_t base = (size_t)bh * TSZ * DH;
    const int tid = threadIdx.x;
    const int ty = tid >> 6;            // 0..3
    const int tx = tid & 63;            // 0..63

    __shared__ float svec[2][5][64];    // double-buffered q,k,v,aK,aC
    __shared__ float redA[4][64], redB[4][64], redC[4][64], redD[4][64];
    __shared__ float ssu[64], sqg[64];

    float Sk[16], Cq[16], G[16];
#pragma unroll
    for (int r = 0; r < 16; r++) { Sk[r] = 0.f; Cq[r] = 0.f; G[r] = 0.f; }

    // per-thread source pointer for the 4 primary vectors
    const float* pb = (tid < 64) ? qp : (tid < 128) ? kp : (tid < 192) ? vp : aKp;

    // prefetch registers: slot s holds (r0, r1) for some timestep
    float pr0[2], pr1[2];
    {
        size_t v0 = base;                      // t = 0
        size_t v1 = base + DH;                 // t = 1
        pr0[0] = pb[v0 + tx];
        pr0[1] = pb[v1 + tx];
        pr1[0] = (tid < 64) ? aCp[v0 + tx] : 0.f;
        pr1[1] = (tid < 64) ? aCp[v1 + tx] : 0.f;
    }
    // store t=0 into buffer 0
    {
        float* svf = &svec[0][0][0];
        svf[tid] = pr0[0];
        if (tid < 64) svf[256 + tid] = pr1[0];
    }
    __syncthreads();

#pragma unroll 2
    for (int t = 0; t < TSZ; t++) {
        const int cur = t & 1;
        const int nxt = cur ^ 1;
        const int ldslot = t & 1;          // slot to refill with t+2
        const int stslot = (t + 1) & 1;    // slot holding t+1 (store this iter)

        // issue prefetch LDG for t+2 (latency covered by ~1.5 steps)
        {
            int tp = t + 2; if (tp > TSZ - 1) tp = TSZ - 1;
            const size_t voff = base + (size_t)tp * DH;
            pr0[ldslot] = pb[voff + tx];
            if (tid < 64) pr1[ldslot] = aCp[voff + tx];
        }

        const float* sq  = svec[cur][0];
        const float* sk  = svec[cur][1];
        const float* sv  = svec[cur][2];
        const float* saK = svec[cur][3];
        const float* saC = svec[cur][4];

        // ---- reduction 1: kc[tx] = sum_i k[i]*aC[i]*Cq_old[i][tx]
        float p1 = 0.f;
#pragma unroll
        for (int r = 0; r < 16; r++) {
            const int i = ty * 16 + r;
            p1 += sk[i] * saC[i] * Cq[r];
        }
        redA[ty][tx] = p1;
        __syncthreads();                                   // S1
        const float kc = redA[0][tx] + redA[1][tx] + redA[2][tx] + redA[3][tx];

        // ---- state updates + partials for u = q^T S_K and qg = q^T G
        const float vtx  = sv[tx];
        const float ktx  = sk[tx];
        const float aKtx = saK[tx];
        float pu = 0.f, pg = 0.f;
#pragma unroll
        for (int r = 0; r < 16; r++) {
            const int i = ty * 16 + r;
            const float qi = sq[i], ki = sk[i], aKi = saK[i], aCi = saC[i];
            Cq[r] = aCi * Cq[r] + qi * vtx;
            G[r]  = aKi * G[r]  + ki * kc;
            Sk[r] = aKi * aKtx * Sk[r] + ki * ktx;
            pu += qi * Sk[r];
            pg += qi * G[r];
        }
        redB[ty][tx] = pu;
        redC[ty][tx] = pg;
        __syncthreads();                                   // S2
        if (ty == 0) {
            ssu[tx] = redB[0][tx] + redB[1][tx] + redB[2][tx] + redB[3][tx];
            sqg[tx] = redC[0][tx] + redC[1][tx] + redC[2][tx] + redC[3][tx];
        }
        // store prefetched t+1 vectors into the other buffer
        {
            float* svf = &svec[nxt][0][0];
            svf[tid] = pr0[stslot];
            if (tid < 64) svf[256 + tid] = pr1[stslot];
        }
        __syncthreads();                                   // S3

        // ---- reduction 3: o[tx] = sum_j su[j]*Cq_new[j][tx] - qg[tx]
        float p3 = 0.f;
#pragma unroll
        for (int r = 0; r < 16; r++) {
            p3 += ssu[ty * 16 + r] * Cq[r];
        }
        redD[ty][tx] = p3;
        __syncthreads();                                   // S4
        if (ty == 0) {
            const float o = redD[0][tx] + redD[1][tx] + redD[2][tx] + redD[3][tx]
                          - sqg[tx];
            o2d[(size_t)(b * TSZ + t) * 1024 + h * DH + tx] = o;
        }
    }
}

// ---------------------------------------------------------------------------
extern "C" void kernel_launch(void* const* d_in, const int* in_sizes, int n_in,
                              void* d_out, int out_size)
{
    const float* x   = (const float*)d_in[0];
    const float* Wq  = (const float*)d_in[1];
    const float* Wk  = (const float*)d_in[2];
    const float* Wv  = (const float*)d_in[3];
    const float* WgK = (const float*)d_in[4];
    const float* bgK = (const float*)d_in[5];
    const float* WgC = (const float*)d_in[6];
    const float* bgC = (const float*)d_in[7];
    const float* Wo  = (const float*)d_in[8];
    float* out = (float*)d_out;

    float* proj = nullptr;
    float* o2d  = nullptr;
    cudaGetSymbolAddress((void**)&proj, g_proj);
    cudaGetSymbolAddress((void**)&o2d,  g_o2d);
    const size_t PS = (size_t)64 * TSZ * DH;

    const int M = 8192, N = 1024, K = 1024;
    dim3 grid(N / 128, M / 128), blk(256);

    gemm_tf32_kernel<<<grid, blk>>>(x, Wq,  nullptr, proj + 0 * PS, M, N, K, 1);
    gemm_tf32_kernel<<<grid, blk>>>(x, Wk,  nullptr, proj + 1 * PS, M, N, K, 1);
    gemm_tf32_kernel<<<grid, blk>>>(x, Wv,  nullptr, proj + 2 * PS, M, N, K, 1);
    gemm_tf32_kernel<<<grid, blk>>>(x, WgK, bgK,     proj + 3 * PS, M, N, K, 2);
    gemm_tf32_kernel<<<grid, blk>>>(x, WgC, bgC,     proj + 4 * PS, M, N, K, 2);

    scan_kernel<<<64, 256>>>(proj, proj + PS, proj + 2 * PS,
                             proj + 3 * PS, proj + 4 * PS, o2d);

    gemm_tf32_kernel<<<grid, blk>>>(o2d, Wo, nullptr, out, M, N, K, 0);
}